// round 4
// baseline (speedup 1.0000x reference)
#include <cuda_runtime.h>
#include <cuda_fp16.h>

#define NN 4096
#define FD 128
#define MAXNBR 128

// Scratch (device globals; no cudaMalloc allowed)
__device__ float          g_S [(size_t)NN * NN];       // 64 MB fp32 S = exp(f^T C f)
__device__ __half         g_Sh[(size_t)NN * NN];       // 32 MB fp16 copy (for gathers)
__device__ unsigned short g_idx[(size_t)NN * MAXNBR];  // 1 MB neighbor lists
__device__ int            g_cnt[NN];

// fast exp on the FMA pipe (degree-7 Taylor of 2^g on [-0.5,0.5]); rel err ~1e-8
__device__ __forceinline__ float fexp(float x) {
    float t = x * 1.4426950408889634f;
    int   ni = __float2int_rn(t);
    float g = t - (float)ni;
    float p =           1.5252734e-5f;
    p = fmaf(p, g,      1.5403530e-4f);
    p = fmaf(p, g,      1.3333558e-3f);
    p = fmaf(p, g,      9.6181291e-3f);
    p = fmaf(p, g,      5.5504109e-2f);
    p = fmaf(p, g,      2.4022651e-1f);
    p = fmaf(p, g,      6.9314718e-1f);
    p = fmaf(p, g,      1.0f);
    return p * __int_as_float((ni + 127) << 23);
}

// ---------------------------------------------------------------------------
// Kernel 0: ordered neighbor-list build. One warp per row, float4 loads,
// warp-inclusive-scan compaction (deterministic).
// ---------------------------------------------------------------------------
__global__ void build_nbr_kernel(const float* __restrict__ nbr) {
    const int warp = threadIdx.x >> 5;
    const int lane = threadIdx.x & 31;
    const int j = blockIdx.x * 8 + warp;
    const float4* row = (const float4*)(nbr + (size_t)j * NN);
    unsigned short* lst = g_idx + (size_t)j * MAXNBR;

    int base = 0;
    #pragma unroll 4
    for (int step = 0; step < NN / 128; ++step) {       // 32 steps, 128 cols each
        int c4 = step * 32 + lane;
        float4 v = row[c4];
        int b0 = v.x != 0.0f, b1 = v.y != 0.0f, b2 = v.z != 0.0f, b3 = v.w != 0.0f;
        int cnt4 = b0 + b1 + b2 + b3;
        int inc = cnt4;
        #pragma unroll
        for (int s = 1; s < 32; s <<= 1) {
            int o = __shfl_up_sync(0xFFFFFFFFu, inc, s);
            if (lane >= s) inc += o;
        }
        int pos = base + inc - cnt4;
        int col = c4 * 4;
        if (b0 && pos < MAXNBR) lst[pos++] = (unsigned short)(col + 0);
        if (b1 && pos < MAXNBR) lst[pos++] = (unsigned short)(col + 1);
        if (b2 && pos < MAXNBR) lst[pos++] = (unsigned short)(col + 2);
        if (b3 && pos < MAXNBR) lst[pos++] = (unsigned short)(col + 3);
        base += __shfl_sync(0xFFFFFFFFu, inc, 31);
    }
    if (lane == 0) g_cnt[j] = min(base, MAXNBR);
}

// ---------------------------------------------------------------------------
// Kernel 1: S = exp(f^T diag(wq*wk) f), symmetric. 128x128 tile per CTA,
// 256 threads, 8x8 per thread, poly exp, dual fp32+fp16 store, mirror via
// smem-staged chunks.
// ---------------------------------------------------------------------------
__global__ void __launch_bounds__(256, 2)
compute_S_kernel(const float* __restrict__ f,
                 const float* __restrict__ wq,
                 const float* __restrict__ wk) {
    const int ti = blockIdx.y;
    const int tj = blockIdx.x;
    if (tj < ti) return;   // upper triangle (mirror written below)

    __shared__ float s_raw[4224];          // max(As+Bs = 4096, stage 32*132)
    __shared__ float cs[FD];
    float* As = s_raw;                     // As[d2][c] : [16][128]
    float* Bs = s_raw + 16 * 128;          // Bs[d2][c] : [16][128]

    const int tid = threadIdx.x;           // 0..255
    const int tx = tid & 15;
    const int ty = tid >> 4;
    const int i0 = ti * 128;
    const int j0 = tj * 128;

    if (tid < FD) cs[tid] = wq[tid] * wk[tid];
    __syncthreads();

    float acc[8][8] = {};

    #pragma unroll 1
    for (int kb = 0; kb < 8; ++kb) {       // 8 chunks of 16 d-slices
        #pragma unroll
        for (int r = 0; r < 2; ++r) {
            int e  = tid + r * 256;        // f4 slot 0..511
            int d2 = e >> 5;
            int c4 = (e & 31) * 4;
            int d  = kb * 16 + d2;
            float cc = cs[d];
            float4 va = *(const float4*)&f[(size_t)d * NN + i0 + c4];
            va.x *= cc; va.y *= cc; va.z *= cc; va.w *= cc;
            *(float4*)&As[d2 * 128 + c4] = va;
            *(float4*)&Bs[d2 * 128 + c4] = *(const float4*)&f[(size_t)d * NN + j0 + c4];
        }
        __syncthreads();

        #pragma unroll
        for (int d2 = 0; d2 < 16; ++d2) {
            float a[8], b[8];
            *(float4*)&a[0] = *(float4*)&As[d2 * 128 + ty * 4];
            *(float4*)&a[4] = *(float4*)&As[d2 * 128 + 64 + ty * 4];
            *(float4*)&b[0] = *(float4*)&Bs[d2 * 128 + tx * 4];
            *(float4*)&b[4] = *(float4*)&Bs[d2 * 128 + 64 + tx * 4];
            #pragma unroll
            for (int r = 0; r < 8; ++r)
                #pragma unroll
                for (int c = 0; c < 8; ++c)
                    acc[r][c] = fmaf(a[r], b[c], acc[r][c]);
        }
        __syncthreads();
    }

    // exponentiate (FMA pipe)
    #pragma unroll
    for (int r = 0; r < 8; ++r)
        #pragma unroll
        for (int c = 0; c < 8; ++c)
            acc[r][c] = fexp(acc[r][c]);

    // primary tile store: fp32 + fp16, coalesced
    #pragma unroll
    for (int rr = 0; rr < 8; ++rr) {
        int rowl = ((rr >> 2) * 64) + ty * 4 + (rr & 3);
        size_t rbase = (size_t)(i0 + rowl) * NN + j0;
        #pragma unroll
        for (int cg = 0; cg < 2; ++cg) {
            float4 w = make_float4(acc[rr][cg * 4 + 0], acc[rr][cg * 4 + 1],
                                   acc[rr][cg * 4 + 2], acc[rr][cg * 4 + 3]);
            int coff = cg * 64 + tx * 4;
            *(float4*)&g_S[rbase + coff] = w;
            __half2 h0 = __floats2half2_rn(w.x, w.y);
            __half2 h1 = __floats2half2_rn(w.z, w.w);
            uint2 u = make_uint2(*(unsigned*)&h0, *(unsigned*)&h1);
            *(uint2*)&g_Sh[rbase + coff] = u;
        }
    }

    // mirror tile (ti != tj): stage transposed 32-column chunks through smem
    if (ti != tj) {
        float* st = s_raw;   // st[jl][il] : [32][132]
        #pragma unroll 1
        for (int q = 0; q < 4; ++q) {
            __syncthreads();
            int cg = q >> 1;
            int txlo = (q & 1) * 8;
            if ((tx >> 3) == (q & 1)) {
                #pragma unroll
                for (int rr = 0; rr < 8; ++rr) {
                    int rowl = ((rr >> 2) * 64) + ty * 4 + (rr & 3);
                    int cb = (tx - txlo) * 4;
                    #pragma unroll
                    for (int cc = 0; cc < 4; ++cc)
                        st[(cb + cc) * 132 + rowl] = acc[rr][cg * 4 + cc];
                }
            }
            __syncthreads();
            #pragma unroll
            for (int w = 0; w < 4; ++w) {
                int e4 = tid + w * 256;
                int jl = e4 >> 5;
                int i4 = (e4 & 31) * 4;
                float4 v = *(float4*)&st[jl * 132 + i4];
                size_t rbase = (size_t)(j0 + q * 32 + jl) * NN + i0;
                *(float4*)&g_S[rbase + i4] = v;
                __half2 h0 = __floats2half2_rn(v.x, v.y);
                __half2 h1 = __floats2half2_rn(v.z, v.w);
                uint2 u = make_uint2(*(unsigned*)&h0, *(unsigned*)&h1);
                *(uint2*)&g_Sh[rbase + i4] = u;
            }
        }
    }
}

// ---------------------------------------------------------------------------
// Kernel 2 (FUSED gather + divide + transpose):
// CTA = 64x64 output tile: columns c0..c0+63 (blockIdx.x), j0..j0+63 (blockIdx.y)
// Thread (tx 0..15, ty 0..15) owns 4 cols x 4 j's (16 fp32 accumulators).
//   D[j,c] = sum_{k in nbr(j)} Sh[k,c]   (fp16 reads, fp32 accum)
//   val    = S[j,c] / D[j,c]             (= out[c,j] by symmetry of S)
// Result transposed through smem; out rows written coalesced.
// ---------------------------------------------------------------------------
__global__ void __launch_bounds__(256)
fused_T_kernel(float* __restrict__ out) {
    __shared__ unsigned short s_idx[64 * MAXNBR];  // 16 KB
    __shared__ int            s_cnt[64];
    __shared__ float          stage[64 * 65];      // 16.25 KB transpose staging

    const int tid = threadIdx.x;
    const int tx  = tid & 15;          // column group: c = c0 + tx*4 + {0..3}
    const int ty  = tid >> 4;          // j group:      j = j0 + ty*4 + {0..3}
    const int c0  = blockIdx.x * 64;
    const int j0  = blockIdx.y * 64;

    // cooperative load of 64 neighbor lists (16 KB contiguous, uint4 copies)
    {
        const uint4* src = (const uint4*)(g_idx + (size_t)j0 * MAXNBR);
        uint4* dst = (uint4*)s_idx;
        #pragma unroll
        for (int e = tid; e < 64 * MAXNBR / 8; e += 256)
            dst[e] = src[e];
        if (tid < 64) s_cnt[tid] = g_cnt[j0 + tid];
    }
    __syncthreads();

    const int cx = c0 + tx * 4;
    float acc[4][4];

    #pragma unroll
    for (int q = 0; q < 4; ++q) {
        const int jl  = ty * 4 + q;
        const int cnt = s_cnt[jl];
        const unsigned short* lst = &s_idx[jl * MAXNBR];

        float a0 = 0.f, a1 = 0.f, a2 = 0.f, a3 = 0.f;
        float b0 = 0.f, b1 = 0.f, b2 = 0.f, b3 = 0.f;
        int k = 0;
        for (; k + 2 <= cnt; k += 2) {
            uint2 h0 = *(const uint2*)&g_Sh[(size_t)lst[k + 0] * NN + cx];
            uint2 h1 = *(const uint2*)&g_Sh[(size_t)lst[k + 1] * NN + cx];
            float2 p;
            p = __half22float2(*(__half2*)&h0.x); a0 += p.x; a1 += p.y;
            p = __half22float2(*(__half2*)&h0.y); a2 += p.x; a3 += p.y;
            p = __half22float2(*(__half2*)&h1.x); b0 += p.x; b1 += p.y;
            p = __half22float2(*(__half2*)&h1.y); b2 += p.x; b3 += p.y;
        }
        if (k < cnt) {
            uint2 h = *(const uint2*)&g_Sh[(size_t)lst[k] * NN + cx];
            float2 p;
            p = __half22float2(*(__half2*)&h.x); a0 += p.x; a1 += p.y;
            p = __half22float2(*(__half2*)&h.y); a2 += p.x; a3 += p.y;
        }
        acc[q][0] = a0 + b0; acc[q][1] = a1 + b1;
        acc[q][2] = a2 + b2; acc[q][3] = a3 + b3;
    }

    // numerator + divide, stage transposed: stage[c_local][j_local]
    #pragma unroll
    for (int q = 0; q < 4; ++q) {
        const int jl = ty * 4 + q;
        float4 s = *(const float4*)&g_S[(size_t)(j0 + jl) * NN + cx];
        stage[(tx * 4 + 0) * 65 + jl] = s.x / acc[q][0];
        stage[(tx * 4 + 1) * 65 + jl] = s.y / acc[q][1];
        stage[(tx * 4 + 2) * 65 + jl] = s.z / acc[q][2];
        stage[(tx * 4 + 3) * 65 + jl] = s.w / acc[q][3];
    }
    __syncthreads();

    // coalesced write: out rows (c0+cl), 64 contiguous j's each
    #pragma unroll
    for (int w = 0; w < 4; ++w) {
        int e  = tid + w * 256;        // 0..1023
        int cl = e >> 4;
        int j4 = (e & 15) * 4;
        float4 v = make_float4(stage[cl * 65 + j4 + 0], stage[cl * 65 + j4 + 1],
                               stage[cl * 65 + j4 + 2], stage[cl * 65 + j4 + 3]);
        *(float4*)&out[(size_t)(c0 + cl) * NN + j0 + j4] = v;
    }
}

// ---------------------------------------------------------------------------
extern "C" void kernel_launch(void* const* d_in, const int* in_sizes, int n_in,
                              void* d_out, int out_size) {
    const float* f   = (const float*)d_in[0];   // [128, 4096]
    const float* nbr = (const float*)d_in[1];   // [4096, 4096]
    const float* wq  = (const float*)d_in[2];   // [128]
    const float* wk  = (const float*)d_in[3];   // [128]
    float* out = (float*)d_out;                 // [4096, 4096]

    build_nbr_kernel<<<NN / 8, 256>>>(nbr);
    compute_S_kernel<<<dim3(32, 32), 256>>>(f, wq, wk);
    fused_T_kernel<<<dim3(NN / 64, NN / 64), 256>>>(out);
}

// round 5
// speedup vs baseline: 1.5350x; 1.5350x over previous
#include <cuda_runtime.h>
#include <cuda_fp16.h>

#define NN 4096
#define FD 128
#define MAXNBR 128

// Scratch (device globals; no cudaMalloc allowed)
__device__ float          g_S [(size_t)NN * NN];       // 64 MB fp32 S = exp(f^T C f)
__device__ __half         g_Sh[(size_t)NN * NN];       // 32 MB fp16 copy (for gathers)
__device__ float          g_T [(size_t)NN * NN];       // 64 MB T = out^T
__device__ unsigned short g_idx[(size_t)NN * MAXNBR];
__device__ int            g_cnt[NN];

// fast exp on the FMA pipe (degree-7 poly of 2^g on [-0.5,0.5]); rel err ~1e-8
__device__ __forceinline__ float fexp(float x) {
    float t = x * 1.4426950408889634f;
    int   ni = __float2int_rn(t);
    float g = t - (float)ni;
    float p =           1.5252734e-5f;
    p = fmaf(p, g,      1.5403530e-4f);
    p = fmaf(p, g,      1.3333558e-3f);
    p = fmaf(p, g,      9.6181291e-3f);
    p = fmaf(p, g,      5.5504109e-2f);
    p = fmaf(p, g,      2.4022651e-1f);
    p = fmaf(p, g,      6.9314718e-1f);
    p = fmaf(p, g,      1.0f);
    return p * __int_as_float((ni + 127) << 23);
}

__device__ __forceinline__ unsigned tf32_rna(float x) {
    unsigned r;
    asm("cvt.rna.tf32.f32 %0, %1;" : "=r"(r) : "f"(x));
    return r;
}

__device__ __forceinline__ void mma_16n8k8(float d[4], const unsigned a[4],
                                           const unsigned b[2]) {
    asm volatile(
        "mma.sync.aligned.m16n8k8.row.col.f32.tf32.tf32.f32 "
        "{%0,%1,%2,%3}, {%4,%5,%6,%7}, {%8,%9}, {%0,%1,%2,%3};"
        : "+f"(d[0]), "+f"(d[1]), "+f"(d[2]), "+f"(d[3])
        : "r"(a[0]), "r"(a[1]), "r"(a[2]), "r"(a[3]), "r"(b[0]), "r"(b[1]));
}

// ---------------------------------------------------------------------------
// Kernel 0: ordered neighbor-list build (warp-scan compaction, deterministic)
// ---------------------------------------------------------------------------
__global__ void build_nbr_kernel(const float* __restrict__ nbr) {
    const int warp = threadIdx.x >> 5;
    const int lane = threadIdx.x & 31;
    const int j = blockIdx.x * 8 + warp;
    const float4* row = (const float4*)(nbr + (size_t)j * NN);
    unsigned short* lst = g_idx + (size_t)j * MAXNBR;

    int base = 0;
    #pragma unroll 4
    for (int step = 0; step < NN / 128; ++step) {
        int c4 = step * 32 + lane;
        float4 v = row[c4];
        int b0 = v.x != 0.0f, b1 = v.y != 0.0f, b2 = v.z != 0.0f, b3 = v.w != 0.0f;
        int cnt4 = b0 + b1 + b2 + b3;
        int inc = cnt4;
        #pragma unroll
        for (int s = 1; s < 32; s <<= 1) {
            int o = __shfl_up_sync(0xFFFFFFFFu, inc, s);
            if (lane >= s) inc += o;
        }
        int pos = base + inc - cnt4;
        int col = c4 * 4;
        if (b0 && pos < MAXNBR) lst[pos++] = (unsigned short)(col + 0);
        if (b1 && pos < MAXNBR) lst[pos++] = (unsigned short)(col + 1);
        if (b2 && pos < MAXNBR) lst[pos++] = (unsigned short)(col + 2);
        if (b3 && pos < MAXNBR) lst[pos++] = (unsigned short)(col + 3);
        base += __shfl_sync(0xFFFFFFFFu, inc, 31);
    }
    if (lane == 0) g_cnt[j] = min(base, MAXNBR);
}

// ---------------------------------------------------------------------------
// Kernel 1: S = exp(f^T diag(wq*wk) f), symmetric — tf32 tensor-core GEMM.
// 128x128 tile per CTA, 8 warps in 2x4 grid (warp = 64 rows x 32 cols),
// m16n8k8 atoms, fp32 accum, poly exp, dual fp32+fp16 store, smem mirror.
// ---------------------------------------------------------------------------
__global__ void __launch_bounds__(256, 2)
compute_S_kernel(const float* __restrict__ f,
                 const float* __restrict__ wq,
                 const float* __restrict__ wk) {
    const int ti = blockIdx.y;
    const int tj = blockIdx.x;
    if (tj < ti) return;   // upper triangle (mirror written below)

    __shared__ float s_raw[2 * 16 * 132];   // As[16][132] | Bs[16][132] (16.9 KB)
    __shared__ float cs[FD];
    float* As = s_raw;
    float* Bs = s_raw + 16 * 132;

    const int tid  = threadIdx.x;            // 0..255
    const int warp = tid >> 5;
    const int lane = tid & 31;
    const int gID  = lane >> 2;               // 0..7
    const int tig  = lane & 3;                // 0..3
    const int wr   = warp >> 2;               // 0..1 : row block (64 rows)
    const int wc   = warp & 3;                // 0..3 : col block (32 cols)
    const int iw   = wr * 64;
    const int jw   = wc * 32;
    const int i0   = ti * 128;
    const int j0   = tj * 128;

    if (tid < FD) cs[tid] = wq[tid] * wk[tid];
    __syncthreads();

    float acc[4][4][4] = {};   // [mi][ni][reg]

    #pragma unroll 1
    for (int kb = 0; kb < 8; ++kb) {          // 8 chunks of 16 k-slices
        #pragma unroll
        for (int r = 0; r < 2; ++r) {
            int e  = tid + r * 256;            // 0..511 float4 slots
            int d2 = e >> 5;
            int c4 = (e & 31) * 4;
            int d  = kb * 16 + d2;
            float cc = cs[d];
            float4 va = *(const float4*)&f[(size_t)d * NN + i0 + c4];
            unsigned* ap = (unsigned*)&As[d2 * 132 + c4];
            ap[0] = tf32_rna(va.x * cc); ap[1] = tf32_rna(va.y * cc);
            ap[2] = tf32_rna(va.z * cc); ap[3] = tf32_rna(va.w * cc);
            float4 vb = *(const float4*)&f[(size_t)d * NN + j0 + c4];
            unsigned* bp = (unsigned*)&Bs[d2 * 132 + c4];
            bp[0] = tf32_rna(vb.x); bp[1] = tf32_rna(vb.y);
            bp[2] = tf32_rna(vb.z); bp[3] = tf32_rna(vb.w);
        }
        __syncthreads();

        #pragma unroll
        for (int k8 = 0; k8 < 2; ++k8) {
            const int kr0 = k8 * 8 + tig;      // k rows tig, tig+4
            unsigned a[4][4];
            #pragma unroll
            for (int mi = 0; mi < 4; ++mi) {
                int ib = iw + mi * 16 + gID;
                a[mi][0] = ((unsigned*)As)[(kr0    ) * 132 + ib];
                a[mi][1] = ((unsigned*)As)[(kr0    ) * 132 + ib + 8];
                a[mi][2] = ((unsigned*)As)[(kr0 + 4) * 132 + ib];
                a[mi][3] = ((unsigned*)As)[(kr0 + 4) * 132 + ib + 8];
            }
            unsigned b[4][2];
            #pragma unroll
            for (int ni = 0; ni < 4; ++ni) {
                int jb = jw + ni * 8 + gID;
                b[ni][0] = ((unsigned*)Bs)[(kr0    ) * 132 + jb];
                b[ni][1] = ((unsigned*)Bs)[(kr0 + 4) * 132 + jb];
            }
            #pragma unroll
            for (int mi = 0; mi < 4; ++mi)
                #pragma unroll
                for (int ni = 0; ni < 4; ++ni)
                    mma_16n8k8(acc[mi][ni], a[mi], b[ni]);
        }
        __syncthreads();
    }

    // exponentiate (FMA pipe)
    #pragma unroll
    for (int mi = 0; mi < 4; ++mi)
        #pragma unroll
        for (int ni = 0; ni < 4; ++ni)
            #pragma unroll
            for (int r = 0; r < 4; ++r)
                acc[mi][ni][r] = fexp(acc[mi][ni][r]);

    // primary tile store: fp32 (float2) + fp16 (half2), per fragment pair
    #pragma unroll
    for (int mi = 0; mi < 4; ++mi) {
        #pragma unroll
        for (int h = 0; h < 2; ++h) {
            int row = i0 + iw + mi * 16 + gID + h * 8;
            size_t rbase = (size_t)row * NN + j0;
            #pragma unroll
            for (int ni = 0; ni < 4; ++ni) {
                int col = jw + ni * 8 + 2 * tig;
                float v0 = acc[mi][ni][h * 2 + 0];
                float v1 = acc[mi][ni][h * 2 + 1];
                *(float2*)&g_S[rbase + col] = make_float2(v0, v1);
                __half2 hh = __floats2half2_rn(v0, v1);
                *(unsigned*)&g_Sh[rbase + col] = *(unsigned*)&hh;
            }
        }
    }

    // mirror tile (ti != tj): stage 32 tile-cols at a time (warp wc==q owns them)
    if (ti != tj) {
        float* st = s_raw;   // st[c_local 0..31][row 0..127], stride 132
        #pragma unroll 1
        for (int q = 0; q < 4; ++q) {
            __syncthreads();
            if (wc == q) {
                #pragma unroll
                for (int mi = 0; mi < 4; ++mi)
                    #pragma unroll
                    for (int h = 0; h < 2; ++h) {
                        int rt = iw + mi * 16 + gID + h * 8;
                        #pragma unroll
                        for (int ni = 0; ni < 4; ++ni) {
                            int cl = ni * 8 + 2 * tig;
                            st[(cl + 0) * 132 + rt] = acc[mi][ni][h * 2 + 0];
                            st[(cl + 1) * 132 + rt] = acc[mi][ni][h * 2 + 1];
                        }
                    }
            }
            __syncthreads();
            #pragma unroll
            for (int w = 0; w < 4; ++w) {
                int e4 = tid + w * 256;            // 0..1023
                int jl = e4 >> 5;                  // 0..31
                int i4 = (e4 & 31) * 4;
                float4 v = *(float4*)&st[jl * 132 + i4];
                size_t rbase = (size_t)(j0 + q * 32 + jl) * NN + i0;
                *(float4*)&g_S[rbase + i4] = v;
                __half2 h0 = __floats2half2_rn(v.x, v.y);
                __half2 h1 = __floats2half2_rn(v.z, v.w);
                uint2 u = make_uint2(*(unsigned*)&h0, *(unsigned*)&h1);
                *(uint2*)&g_Sh[rbase + i4] = u;
            }
        }
    }
}

// ---------------------------------------------------------------------------
// Kernel 2: per row j: D[j,:] = sum_{k in nbr(j)} Sh[k,:] (fp16 reads, fp32
// accum);  T[j,:] = S[j,:]/D[j,:].  One CTA per j, 512 threads x 8 cols.
// ---------------------------------------------------------------------------
__device__ __forceinline__ void add8(float* acc, uint4 h) {
    float2 p;
    p = __half22float2(*(__half2*)&h.x); acc[0] += p.x; acc[1] += p.y;
    p = __half22float2(*(__half2*)&h.y); acc[2] += p.x; acc[3] += p.y;
    p = __half22float2(*(__half2*)&h.z); acc[4] += p.x; acc[5] += p.y;
    p = __half22float2(*(__half2*)&h.w); acc[6] += p.x; acc[7] += p.y;
}

__global__ void __launch_bounds__(512)
compute_T_kernel() {
    const int j = blockIdx.x;
    __shared__ unsigned short s_idx[MAXNBR];
    __shared__ int s_cnt;
    const int tid = threadIdx.x;

    if (tid == 0) s_cnt = g_cnt[j];
    if (tid < MAXNBR) s_idx[tid] = g_idx[(size_t)j * MAXNBR + tid];
    __syncthreads();
    const int cnt = s_cnt;
    const int c8 = tid * 8;

    float acc[8] = {};
    int k = 0;
    for (; k + 4 <= cnt; k += 4) {
        uint4 h0 = *(const uint4*)&g_Sh[(size_t)s_idx[k + 0] * NN + c8];
        uint4 h1 = *(const uint4*)&g_Sh[(size_t)s_idx[k + 1] * NN + c8];
        uint4 h2 = *(const uint4*)&g_Sh[(size_t)s_idx[k + 2] * NN + c8];
        uint4 h3 = *(const uint4*)&g_Sh[(size_t)s_idx[k + 3] * NN + c8];
        add8(acc, h0); add8(acc, h1); add8(acc, h2); add8(acc, h3);
    }
    for (; k < cnt; ++k) {
        uint4 h = *(const uint4*)&g_Sh[(size_t)s_idx[k] * NN + c8];
        add8(acc, h);
    }

    float4 s0 = *(const float4*)&g_S[(size_t)j * NN + c8];
    float4 s1 = *(const float4*)&g_S[(size_t)j * NN + c8 + 4];
    *(float4*)&g_T[(size_t)j * NN + c8] =
        make_float4(s0.x / acc[0], s0.y / acc[1], s0.z / acc[2], s0.w / acc[3]);
    *(float4*)&g_T[(size_t)j * NN + c8 + 4] =
        make_float4(s1.x / acc[4], s1.y / acc[5], s1.z / acc[6], s1.w / acc[7]);
}

// ---------------------------------------------------------------------------
// Kernel 3: out = T^T.  64x64 tiles, float4 loads/stores, 256 threads.
// ---------------------------------------------------------------------------
__global__ void transpose_kernel(float* __restrict__ out) {
    __shared__ float tile[64][65];
    const int tx = threadIdx.x & 15;
    const int ty = threadIdx.x >> 4;
    const int bx = blockIdx.x, by = blockIdx.y;

    #pragma unroll
    for (int s = 0; s < 4; ++s) {
        int r = s * 16 + ty;
        float4 v = *(const float4*)&g_T[(size_t)(by * 64 + r) * NN + bx * 64 + tx * 4];
        tile[r][tx * 4 + 0] = v.x;
        tile[r][tx * 4 + 1] = v.y;
        tile[r][tx * 4 + 2] = v.z;
        tile[r][tx * 4 + 3] = v.w;
    }
    __syncthreads();
    #pragma unroll
    for (int s = 0; s < 4; ++s) {
        int r = s * 16 + ty;
        float4 w = make_float4(tile[tx * 4 + 0][r], tile[tx * 4 + 1][r],
                               tile[tx * 4 + 2][r], tile[tx * 4 + 3][r]);
        *(float4*)&out[(size_t)(bx * 64 + r) * NN + by * 64 + tx * 4] = w;
    }
}

// ---------------------------------------------------------------------------
extern "C" void kernel_launch(void* const* d_in, const int* in_sizes, int n_in,
                              void* d_out, int out_size) {
    const float* f   = (const float*)d_in[0];   // [128, 4096]
    const float* nbr = (const float*)d_in[1];   // [4096, 4096]
    const float* wq  = (const float*)d_in[2];   // [128]
    const float* wk  = (const float*)d_in[3];   // [128]
    float* out = (float*)d_out;                 // [4096, 4096]

    build_nbr_kernel<<<NN / 8, 256>>>(nbr);
    compute_S_kernel<<<dim3(32, 32), 256>>>(f, wq, wk);
    compute_T_kernel<<<NN, 512>>>();
    transpose_kernel<<<dim3(NN / 64, NN / 64), 256>>>(out);
}

// round 6
// speedup vs baseline: 1.5770x; 1.0274x over previous
#include <cuda_runtime.h>
#include <cuda_fp16.h>

#define NN 4096
#define FD 128
#define MAXNBR 128

// Scratch (device globals; no cudaMalloc allowed)
__device__ float          g_S [(size_t)NN * NN];       // 64 MB fp32 S = exp(f^T C f)
__device__ __half         g_Sh[(size_t)NN * NN];       // 32 MB fp16 copy (for gathers)
__device__ unsigned short g_idx[(size_t)NN * MAXNBR];
__device__ int            g_cnt[NN];

// fast exp on the FMA pipe (degree-7 poly of 2^g on [-0.5,0.5]); rel err ~1e-8
__device__ __forceinline__ float fexp(float x) {
    float t = x * 1.4426950408889634f;
    int   ni = __float2int_rn(t);
    float g = t - (float)ni;
    float p =           1.5252734e-5f;
    p = fmaf(p, g,      1.5403530e-4f);
    p = fmaf(p, g,      1.3333558e-3f);
    p = fmaf(p, g,      9.6181291e-3f);
    p = fmaf(p, g,      5.5504109e-2f);
    p = fmaf(p, g,      2.4022651e-1f);
    p = fmaf(p, g,      6.9314718e-1f);
    p = fmaf(p, g,      1.0f);
    return p * __int_as_float((ni + 127) << 23);
}

__device__ __forceinline__ unsigned tf32_rna(float x) {
    unsigned r;
    asm("cvt.rna.tf32.f32 %0, %1;" : "=r"(r) : "f"(x));
    return r;
}

__device__ __forceinline__ void mma_16n8k8(float d[4], const unsigned a[4],
                                           const unsigned b[2]) {
    asm volatile(
        "mma.sync.aligned.m16n8k8.row.col.f32.tf32.tf32.f32 "
        "{%0,%1,%2,%3}, {%4,%5,%6,%7}, {%8,%9}, {%0,%1,%2,%3};"
        : "+f"(d[0]), "+f"(d[1]), "+f"(d[2]), "+f"(d[3])
        : "r"(a[0]), "r"(a[1]), "r"(a[2]), "r"(a[3]), "r"(b[0]), "r"(b[1]));
}

// ---------------------------------------------------------------------------
// Kernel 0: ordered neighbor-list build (warp-scan compaction, deterministic)
// Loads hoisted 4-deep ahead of the serial scan chain for MLP.
// ---------------------------------------------------------------------------
__global__ void build_nbr_kernel(const float* __restrict__ nbr) {
    const int warp = threadIdx.x >> 5;
    const int lane = threadIdx.x & 31;
    const int j = blockIdx.x * 8 + warp;
    const float4* row = (const float4*)(nbr + (size_t)j * NN);
    unsigned short* lst = g_idx + (size_t)j * MAXNBR;

    int base = 0;
    #pragma unroll 1
    for (int step = 0; step < 8; ++step) {
        float4 v[4];
        #pragma unroll
        for (int u = 0; u < 4; ++u)
            v[u] = row[(step * 4 + u) * 32 + lane];   // 4 loads in flight

        #pragma unroll
        for (int u = 0; u < 4; ++u) {
            int c4 = (step * 4 + u) * 32 + lane;
            int b0 = v[u].x != 0.0f, b1 = v[u].y != 0.0f,
                b2 = v[u].z != 0.0f, b3 = v[u].w != 0.0f;
            int cnt4 = b0 + b1 + b2 + b3;
            int inc = cnt4;
            #pragma unroll
            for (int s = 1; s < 32; s <<= 1) {
                int o = __shfl_up_sync(0xFFFFFFFFu, inc, s);
                if (lane >= s) inc += o;
            }
            int pos = base + inc - cnt4;
            int col = c4 * 4;
            if (b0 && pos < MAXNBR) lst[pos++] = (unsigned short)(col + 0);
            if (b1 && pos < MAXNBR) lst[pos++] = (unsigned short)(col + 1);
            if (b2 && pos < MAXNBR) lst[pos++] = (unsigned short)(col + 2);
            if (b3 && pos < MAXNBR) lst[pos++] = (unsigned short)(col + 3);
            base += __shfl_sync(0xFFFFFFFFu, inc, 31);
        }
    }
    if (lane == 0) g_cnt[j] = min(base, MAXNBR);
}

// ---------------------------------------------------------------------------
// Kernel 1: S = exp(f^T diag(wq*wk) f), symmetric — tf32 tensor-core GEMM.
// 128x128 tile per CTA, 8 warps (2x4), m16n8k8 atoms, poly exp,
// dual fp32+fp16 store, smem-staged mirror.  (unchanged from round 5)
// ---------------------------------------------------------------------------
__global__ void __launch_bounds__(256, 2)
compute_S_kernel(const float* __restrict__ f,
                 const float* __restrict__ wq,
                 const float* __restrict__ wk) {
    const int ti = blockIdx.y;
    const int tj = blockIdx.x;
    if (tj < ti) return;   // upper triangle (mirror written below)

    __shared__ float s_raw[2 * 16 * 132];   // As[16][132] | Bs[16][132]
    __shared__ float cs[FD];
    float* As = s_raw;
    float* Bs = s_raw + 16 * 132;

    const int tid  = threadIdx.x;
    const int warp = tid >> 5;
    const int lane = tid & 31;
    const int gID  = lane >> 2;
    const int tig  = lane & 3;
    const int wr   = warp >> 2;
    const int wc   = warp & 3;
    const int iw   = wr * 64;
    const int jw   = wc * 32;
    const int i0   = ti * 128;
    const int j0   = tj * 128;

    if (tid < FD) cs[tid] = wq[tid] * wk[tid];
    __syncthreads();

    float acc[4][4][4] = {};

    #pragma unroll 1
    for (int kb = 0; kb < 8; ++kb) {
        #pragma unroll
        for (int r = 0; r < 2; ++r) {
            int e  = tid + r * 256;
            int d2 = e >> 5;
            int c4 = (e & 31) * 4;
            int d  = kb * 16 + d2;
            float cc = cs[d];
            float4 va = *(const float4*)&f[(size_t)d * NN + i0 + c4];
            unsigned* ap = (unsigned*)&As[d2 * 132 + c4];
            ap[0] = tf32_rna(va.x * cc); ap[1] = tf32_rna(va.y * cc);
            ap[2] = tf32_rna(va.z * cc); ap[3] = tf32_rna(va.w * cc);
            float4 vb = *(const float4*)&f[(size_t)d * NN + j0 + c4];
            unsigned* bp = (unsigned*)&Bs[d2 * 132 + c4];
            bp[0] = tf32_rna(vb.x); bp[1] = tf32_rna(vb.y);
            bp[2] = tf32_rna(vb.z); bp[3] = tf32_rna(vb.w);
        }
        __syncthreads();

        #pragma unroll
        for (int k8 = 0; k8 < 2; ++k8) {
            const int kr0 = k8 * 8 + tig;
            unsigned a[4][4];
            #pragma unroll
            for (int mi = 0; mi < 4; ++mi) {
                int ib = iw + mi * 16 + gID;
                a[mi][0] = ((unsigned*)As)[(kr0    ) * 132 + ib];
                a[mi][1] = ((unsigned*)As)[(kr0    ) * 132 + ib + 8];
                a[mi][2] = ((unsigned*)As)[(kr0 + 4) * 132 + ib];
                a[mi][3] = ((unsigned*)As)[(kr0 + 4) * 132 + ib + 8];
            }
            unsigned b[4][2];
            #pragma unroll
            for (int ni = 0; ni < 4; ++ni) {
                int jb = jw + ni * 8 + gID;
                b[ni][0] = ((unsigned*)Bs)[(kr0    ) * 132 + jb];
                b[ni][1] = ((unsigned*)Bs)[(kr0 + 4) * 132 + jb];
            }
            #pragma unroll
            for (int mi = 0; mi < 4; ++mi)
                #pragma unroll
                for (int ni = 0; ni < 4; ++ni)
                    mma_16n8k8(acc[mi][ni], a[mi], b[ni]);
        }
        __syncthreads();
    }

    #pragma unroll
    for (int mi = 0; mi < 4; ++mi)
        #pragma unroll
        for (int ni = 0; ni < 4; ++ni)
            #pragma unroll
            for (int r = 0; r < 4; ++r)
                acc[mi][ni][r] = fexp(acc[mi][ni][r]);

    #pragma unroll
    for (int mi = 0; mi < 4; ++mi) {
        #pragma unroll
        for (int h = 0; h < 2; ++h) {
            int row = i0 + iw + mi * 16 + gID + h * 8;
            size_t rbase = (size_t)row * NN + j0;
            #pragma unroll
            for (int ni = 0; ni < 4; ++ni) {
                int col = jw + ni * 8 + 2 * tig;
                float v0 = acc[mi][ni][h * 2 + 0];
                float v1 = acc[mi][ni][h * 2 + 1];
                *(float2*)&g_S[rbase + col] = make_float2(v0, v1);
                __half2 hh = __floats2half2_rn(v0, v1);
                *(unsigned*)&g_Sh[rbase + col] = *(unsigned*)&hh;
            }
        }
    }

    if (ti != tj) {
        float* st = s_raw;   // st[c_local 0..31][row 0..127], stride 132
        #pragma unroll 1
        for (int q = 0; q < 4; ++q) {
            __syncthreads();
            if (wc == q) {
                #pragma unroll
                for (int mi = 0; mi < 4; ++mi)
                    #pragma unroll
                    for (int h = 0; h < 2; ++h) {
                        int rt = iw + mi * 16 + gID + h * 8;
                        #pragma unroll
                        for (int ni = 0; ni < 4; ++ni) {
                            int cl = ni * 8 + 2 * tig;
                            st[(cl + 0) * 132 + rt] = acc[mi][ni][h * 2 + 0];
                            st[(cl + 1) * 132 + rt] = acc[mi][ni][h * 2 + 1];
                        }
                    }
            }
            __syncthreads();
            #pragma unroll
            for (int w = 0; w < 4; ++w) {
                int e4 = tid + w * 256;
                int jl = e4 >> 5;
                int i4 = (e4 & 31) * 4;
                float4 v = *(float4*)&st[jl * 132 + i4];
                size_t rbase = (size_t)(j0 + q * 32 + jl) * NN + i0;
                *(float4*)&g_S[rbase + i4] = v;
                __half2 h0 = __floats2half2_rn(v.x, v.y);
                __half2 h1 = __floats2half2_rn(v.z, v.w);
                uint2 u = make_uint2(*(unsigned*)&h0, *(unsigned*)&h1);
                *(uint2*)&g_Sh[rbase + i4] = u;
            }
        }
    }
}

// ---------------------------------------------------------------------------
// Kernel 2 (FUSED gather + divide + transposed write):
// CTA = 32 j's (blockIdx.y) x 128 cols (blockIdx.x), 512 threads.
// Thread (jt = tid>>4, cg = tid&15) owns j = j0+jt, cols c8 = c0+cg*8..+7 —
// the SAME inner-loop shape as the fast compute_T (uint4 loads, MLP 4).
//   D[j,c] = sum_{k in nbr(j)} Sh[k,c]; val = S[j,c]/D[j,c] = out[c,j].
// Results transposed through smem; out rows written coalesced.
// ---------------------------------------------------------------------------
__device__ __forceinline__ void add8(float* acc, uint4 h) {
    float2 p;
    p = __half22float2(*(__half2*)&h.x); acc[0] += p.x; acc[1] += p.y;
    p = __half22float2(*(__half2*)&h.y); acc[2] += p.x; acc[3] += p.y;
    p = __half22float2(*(__half2*)&h.z); acc[4] += p.x; acc[5] += p.y;
    p = __half22float2(*(__half2*)&h.w); acc[6] += p.x; acc[7] += p.y;
}

__global__ void __launch_bounds__(512)
fused_T_kernel(float* __restrict__ out) {
    __shared__ unsigned short s_idx[32 * MAXNBR];   // 8 KB
    __shared__ int            s_cnt[32];
    __shared__ float          stage[32 * 129];      // 16.5 KB  [jt][cl]

    const int tid = threadIdx.x;
    const int cg  = tid & 15;          // column group (8 cols)
    const int jt  = tid >> 4;          // 0..31
    const int c0  = blockIdx.x * 128;
    const int j0  = blockIdx.y * 32;

    // cooperative load of 32 neighbor lists (8 KB contiguous): 1 uint4/thread
    {
        const uint4* src = (const uint4*)(g_idx + (size_t)j0 * MAXNBR);
        ((uint4*)s_idx)[tid] = src[tid];
        if (tid < 32) s_cnt[tid] = g_cnt[j0 + tid];
    }
    __syncthreads();

    const int j   = j0 + jt;
    const int cnt = s_cnt[jt];
    const unsigned short* lst = &s_idx[jt * MAXNBR];
    const int c8 = c0 + cg * 8;

    float acc[8] = {};
    int k = 0;
    for (; k + 4 <= cnt; k += 4) {
        uint4 h0 = *(const uint4*)&g_Sh[(size_t)lst[k + 0] * NN + c8];
        uint4 h1 = *(const uint4*)&g_Sh[(size_t)lst[k + 1] * NN + c8];
        uint4 h2 = *(const uint4*)&g_Sh[(size_t)lst[k + 2] * NN + c8];
        uint4 h3 = *(const uint4*)&g_Sh[(size_t)lst[k + 3] * NN + c8];
        add8(acc, h0); add8(acc, h1); add8(acc, h2); add8(acc, h3);
    }
    for (; k < cnt; ++k) {
        uint4 h = *(const uint4*)&g_Sh[(size_t)lst[k] * NN + c8];
        add8(acc, h);
    }

    // numerator, divide, stage [jt][cl]
    float4 s0 = *(const float4*)&g_S[(size_t)j * NN + c8];
    float4 s1 = *(const float4*)&g_S[(size_t)j * NN + c8 + 4];
    float* sp = &stage[jt * 129 + cg * 8];
    sp[0] = s0.x / acc[0]; sp[1] = s0.y / acc[1];
    sp[2] = s0.z / acc[2]; sp[3] = s0.w / acc[3];
    sp[4] = s1.x / acc[4]; sp[5] = s1.y / acc[5];
    sp[6] = s1.z / acc[6]; sp[7] = s1.w / acc[7];
    __syncthreads();

    // transposed write: out rows c0+cl (128 rows), 32 contiguous j's each
    #pragma unroll
    for (int w = 0; w < 2; ++w) {
        int e  = tid + w * 512;        // 0..1023
        int cl = e >> 3;               // 0..127
        int j4 = (e & 7) * 4;          // 0..28
        float4 v = make_float4(stage[(j4 + 0) * 129 + cl],
                               stage[(j4 + 1) * 129 + cl],
                               stage[(j4 + 2) * 129 + cl],
                               stage[(j4 + 3) * 129 + cl]);
        *(float4*)&out[(size_t)(c0 + cl) * NN + j0 + j4] = v;
    }
}

// ---------------------------------------------------------------------------
extern "C" void kernel_launch(void* const* d_in, const int* in_sizes, int n_in,
                              void* d_out, int out_size) {
    const float* f   = (const float*)d_in[0];   // [128, 4096]
    const float* nbr = (const float*)d_in[1];   // [4096, 4096]
    const float* wq  = (const float*)d_in[2];   // [128]
    const float* wk  = (const float*)d_in[3];   // [128]
    float* out = (float*)d_out;                 // [4096, 4096]

    build_nbr_kernel<<<NN / 8, 256>>>(nbr);
    compute_S_kernel<<<dim3(32, 32), 256>>>(f, wq, wk);
    fused_T_kernel<<<dim3(NN / 128, NN / 32), 512>>>(out);
}

// round 7
// speedup vs baseline: 1.6522x; 1.0477x over previous
#include <cuda_runtime.h>
#include <cuda_fp16.h>

#define NN 4096
#define FD 128
#define MAXNBR 128

// Scratch (device globals; no cudaMalloc allowed). Total hot set = 33 MB,
// fully L2-resident (126 MB L2, persistent across kernel launches).
__device__ __half         g_Sh[(size_t)NN * NN];       // 32 MB fp16 S = exp(f^T C f)
__device__ unsigned short g_idx[(size_t)NN * MAXNBR];  // front/back packed lists
__device__ int            g_cnt0[NN];                  // front-segment count (warp 0)
__device__ int            g_cnt1[NN];                  // back-segment count (warp 1)

// fast exp on the FMA pipe (degree-7 poly of 2^g on [-0.5,0.5]); rel err ~1e-8
__device__ __forceinline__ float fexp(float x) {
    float t = x * 1.4426950408889634f;
    int   ni = __float2int_rn(t);
    float g = t - (float)ni;
    float p =           1.5252734e-5f;
    p = fmaf(p, g,      1.5403530e-4f);
    p = fmaf(p, g,      1.3333558e-3f);
    p = fmaf(p, g,      9.6181291e-3f);
    p = fmaf(p, g,      5.5504109e-2f);
    p = fmaf(p, g,      2.4022651e-1f);
    p = fmaf(p, g,      6.9314718e-1f);
    p = fmaf(p, g,      1.0f);
    return p * __int_as_float((ni + 127) << 23);
}

__device__ __forceinline__ unsigned tf32_rna(float x) {
    unsigned r;
    asm("cvt.rna.tf32.f32 %0, %1;" : "=r"(r) : "f"(x));
    return r;
}

__device__ __forceinline__ void mma_16n8k8(float d[4], const unsigned a[4],
                                           const unsigned b[2]) {
    asm volatile(
        "mma.sync.aligned.m16n8k8.row.col.f32.tf32.tf32.f32 "
        "{%0,%1,%2,%3}, {%4,%5,%6,%7}, {%8,%9}, {%0,%1,%2,%3};"
        : "+f"(d[0]), "+f"(d[1]), "+f"(d[2]), "+f"(d[3])
        : "r"(a[0]), "r"(a[1]), "r"(a[2]), "r"(a[3]), "r"(b[0]), "r"(b[1]));
}

// ---------------------------------------------------------------------------
// Kernel 0: neighbor-list build. 2 warps per row (front/back halves),
// ballot+popc compaction (no serial scan). w0 fills lst[0..c0) forward,
// w1 fills lst[MAXNBR-c1..MAXNBR) backward. Order is deterministic
// (sum order doesn't matter for the fp32 neighbor sum).
// ---------------------------------------------------------------------------
__global__ void build_nbr_kernel(const float* __restrict__ nbr) {
    const int warp = threadIdx.x >> 5;        // 0..7
    const int lane = threadIdx.x & 31;
    const int rloc = warp >> 1;                // row within CTA 0..3
    const int h    = warp & 1;                 // half selector
    const int j    = blockIdx.x * 4 + rloc;
    const float4* row = (const float4*)(nbr + (size_t)j * NN) + h * 512;
    unsigned short* lst = g_idx + (size_t)j * MAXNBR;
    const unsigned lt = (1u << lane) - 1u;
    const int colbase = h * 2048;

    int base = 0;
    #pragma unroll 1
    for (int step = 0; step < 4; ++step) {
        float4 v[4];
        #pragma unroll
        for (int u = 0; u < 4; ++u)
            v[u] = row[(step * 4 + u) * 32 + lane];      // 4 loads in flight

        #pragma unroll
        for (int u = 0; u < 4; ++u) {
            int col = colbase + ((step * 4 + u) * 32 + lane) * 4;
            unsigned m0 = __ballot_sync(0xFFFFFFFFu, v[u].x != 0.0f);
            unsigned m1 = __ballot_sync(0xFFFFFFFFu, v[u].y != 0.0f);
            unsigned m2 = __ballot_sync(0xFFFFFFFFu, v[u].z != 0.0f);
            unsigned m3 = __ballot_sync(0xFFFFFFFFu, v[u].w != 0.0f);
            int t0 = __popc(m0), t1 = __popc(m1), t2 = __popc(m2), t3 = __popc(m3);
            int p0 = base + __popc(m0 & lt);
            int p1 = base + t0 + __popc(m1 & lt);
            int p2 = base + t0 + t1 + __popc(m2 & lt);
            int p3 = base + t0 + t1 + t2 + __popc(m3 & lt);
            if (h == 0) {
                if ((m0 >> lane) & 1 && p0 < MAXNBR) lst[p0] = (unsigned short)(col + 0);
                if ((m1 >> lane) & 1 && p1 < MAXNBR) lst[p1] = (unsigned short)(col + 1);
                if ((m2 >> lane) & 1 && p2 < MAXNBR) lst[p2] = (unsigned short)(col + 2);
                if ((m3 >> lane) & 1 && p3 < MAXNBR) lst[p3] = (unsigned short)(col + 3);
            } else {
                if ((m0 >> lane) & 1 && p0 < MAXNBR) lst[MAXNBR - 1 - p0] = (unsigned short)(col + 0);
                if ((m1 >> lane) & 1 && p1 < MAXNBR) lst[MAXNBR - 1 - p1] = (unsigned short)(col + 1);
                if ((m2 >> lane) & 1 && p2 < MAXNBR) lst[MAXNBR - 1 - p2] = (unsigned short)(col + 2);
                if ((m3 >> lane) & 1 && p3 < MAXNBR) lst[MAXNBR - 1 - p3] = (unsigned short)(col + 3);
            }
            base += t0 + t1 + t2 + t3;
        }
    }
    if (lane == 0) {
        int c = min(base, MAXNBR);
        if (h == 0) g_cnt0[j] = c; else g_cnt1[j] = c;
    }
}

// ---------------------------------------------------------------------------
// Kernel 1: S = exp(f^T diag(wq*wk) f), symmetric — tf32 tensor-core GEMM.
// 128x128 tile per CTA, 8 warps (2x4), m16n8k8 atoms, poly exp,
// fp16-only store (primary + smem-staged mirror).
// ---------------------------------------------------------------------------
__global__ void __launch_bounds__(256, 2)
compute_S_kernel(const float* __restrict__ f,
                 const float* __restrict__ wq,
                 const float* __restrict__ wk) {
    const int ti = blockIdx.y;
    const int tj = blockIdx.x;
    if (tj < ti) return;   // upper triangle (mirror written below)

    __shared__ float s_raw[2 * 16 * 132];   // As[16][132] | Bs[16][132]
    __shared__ float cs[FD];
    float* As = s_raw;
    float* Bs = s_raw + 16 * 132;

    const int tid  = threadIdx.x;
    const int warp = tid >> 5;
    const int lane = tid & 31;
    const int gID  = lane >> 2;
    const int tig  = lane & 3;
    const int wr   = warp >> 2;
    const int wc   = warp & 3;
    const int iw   = wr * 64;
    const int jw   = wc * 32;
    const int i0   = ti * 128;
    const int j0   = tj * 128;

    if (tid < FD) cs[tid] = wq[tid] * wk[tid];
    __syncthreads();

    float acc[4][4][4] = {};

    #pragma unroll 1
    for (int kb = 0; kb < 8; ++kb) {
        #pragma unroll
        for (int r = 0; r < 2; ++r) {
            int e  = tid + r * 256;
            int d2 = e >> 5;
            int c4 = (e & 31) * 4;
            int d  = kb * 16 + d2;
            float cc = cs[d];
            float4 va = *(const float4*)&f[(size_t)d * NN + i0 + c4];
            unsigned* ap = (unsigned*)&As[d2 * 132 + c4];
            ap[0] = tf32_rna(va.x * cc); ap[1] = tf32_rna(va.y * cc);
            ap[2] = tf32_rna(va.z * cc); ap[3] = tf32_rna(va.w * cc);
            float4 vb = *(const float4*)&f[(size_t)d * NN + j0 + c4];
            unsigned* bp = (unsigned*)&Bs[d2 * 132 + c4];
            bp[0] = tf32_rna(vb.x); bp[1] = tf32_rna(vb.y);
            bp[2] = tf32_rna(vb.z); bp[3] = tf32_rna(vb.w);
        }
        __syncthreads();

        #pragma unroll
        for (int k8 = 0; k8 < 2; ++k8) {
            const int kr0 = k8 * 8 + tig;
            unsigned a[4][4];
            #pragma unroll
            for (int mi = 0; mi < 4; ++mi) {
                int ib = iw + mi * 16 + gID;
                a[mi][0] = ((unsigned*)As)[(kr0    ) * 132 + ib];
                a[mi][1] = ((unsigned*)As)[(kr0    ) * 132 + ib + 8];
                a[mi][2] = ((unsigned*)As)[(kr0 + 4) * 132 + ib];
                a[mi][3] = ((unsigned*)As)[(kr0 + 4) * 132 + ib + 8];
            }
            unsigned b[4][2];
            #pragma unroll
            for (int ni = 0; ni < 4; ++ni) {
                int jb = jw + ni * 8 + gID;
                b[ni][0] = ((unsigned*)Bs)[(kr0    ) * 132 + jb];
                b[ni][1] = ((unsigned*)Bs)[(kr0 + 4) * 132 + jb];
            }
            #pragma unroll
            for (int mi = 0; mi < 4; ++mi)
                #pragma unroll
                for (int ni = 0; ni < 4; ++ni)
                    mma_16n8k8(acc[mi][ni], a[mi], b[ni]);
        }
        __syncthreads();
    }

    #pragma unroll
    for (int mi = 0; mi < 4; ++mi)
        #pragma unroll
        for (int ni = 0; ni < 4; ++ni)
            #pragma unroll
            for (int r = 0; r < 4; ++r)
                acc[mi][ni][r] = fexp(acc[mi][ni][r]);

    // primary tile store: fp16 half2 per fragment pair
    #pragma unroll
    for (int mi = 0; mi < 4; ++mi) {
        #pragma unroll
        for (int h = 0; h < 2; ++h) {
            int row = i0 + iw + mi * 16 + gID + h * 8;
            size_t rbase = (size_t)row * NN + j0;
            #pragma unroll
            for (int ni = 0; ni < 4; ++ni) {
                int col = jw + ni * 8 + 2 * tig;
                __half2 hh = __floats2half2_rn(acc[mi][ni][h * 2 + 0],
                                               acc[mi][ni][h * 2 + 1]);
                *(unsigned*)&g_Sh[rbase + col] = *(unsigned*)&hh;
            }
        }
    }

    // mirror tile (ti != tj): stage 32 tile-cols at a time
    if (ti != tj) {
        float* st = s_raw;   // st[c_local 0..31][row 0..127], stride 132
        #pragma unroll 1
        for (int q = 0; q < 4; ++q) {
            __syncthreads();
            if (wc == q) {
                #pragma unroll
                for (int mi = 0; mi < 4; ++mi)
                    #pragma unroll
                    for (int h = 0; h < 2; ++h) {
                        int rt = iw + mi * 16 + gID + h * 8;
                        #pragma unroll
                        for (int ni = 0; ni < 4; ++ni) {
                            int cl = ni * 8 + 2 * tig;
                            st[(cl + 0) * 132 + rt] = acc[mi][ni][h * 2 + 0];
                            st[(cl + 1) * 132 + rt] = acc[mi][ni][h * 2 + 1];
                        }
                    }
            }
            __syncthreads();
            #pragma unroll
            for (int w = 0; w < 4; ++w) {
                int e4 = tid + w * 256;
                int jl = e4 >> 5;
                int i4 = (e4 & 31) * 4;
                float4 v = *(float4*)&st[jl * 132 + i4];
                size_t rbase = (size_t)(j0 + q * 32 + jl) * NN + i0;
                __half2 h0 = __floats2half2_rn(v.x, v.y);
                __half2 h1 = __floats2half2_rn(v.z, v.w);
                uint2 u = make_uint2(*(unsigned*)&h0, *(unsigned*)&h1);
                *(uint2*)&g_Sh[rbase + i4] = u;
            }
        }
    }
}

// ---------------------------------------------------------------------------
// Kernel 2 (FUSED gather + divide + transposed write), all-fp16 source:
// CTA = 32 j's x 128 cols, 512 threads; thread = (1 j, 8 cols).
//   D[j,c] = sum_{k in nbr(j)} Sh[k,c]  (fp16 reads, fp32 accum, MLP 4)
//   val    = Sh[j,c] / D[j,c]  (= out[c,j] by symmetry of S)
// Neighbor list has front [0,cnt0) and back [MAXNBR-cnt1,MAXNBR) segments.
// ---------------------------------------------------------------------------
__device__ __forceinline__ void add8(float* acc, uint4 h) {
    float2 p;
    p = __half22float2(*(__half2*)&h.x); acc[0] += p.x; acc[1] += p.y;
    p = __half22float2(*(__half2*)&h.y); acc[2] += p.x; acc[3] += p.y;
    p = __half22float2(*(__half2*)&h.z); acc[4] += p.x; acc[5] += p.y;
    p = __half22float2(*(__half2*)&h.w); acc[6] += p.x; acc[7] += p.y;
}

__global__ void __launch_bounds__(512)
fused_T_kernel(float* __restrict__ out) {
    __shared__ unsigned short s_idx[32 * MAXNBR];   // 8 KB
    __shared__ int            s_c0[32];
    __shared__ int            s_c1[32];
    __shared__ float          stage[32 * 129];      // 16.5 KB  [jt][cl]

    const int tid = threadIdx.x;
    const int cg  = tid & 15;          // column group (8 cols)
    const int jt  = tid >> 4;          // 0..31
    const int c0  = blockIdx.x * 128;
    const int j0  = blockIdx.y * 32;

    {
        const uint4* src = (const uint4*)(g_idx + (size_t)j0 * MAXNBR);
        ((uint4*)s_idx)[tid] = src[tid];
        if (tid < 32) { s_c0[tid] = g_cnt0[j0 + tid]; s_c1[tid] = g_cnt1[j0 + tid]; }
    }
    __syncthreads();

    const int j    = j0 + jt;
    const int cnt0 = s_c0[jt];
    const int cnt  = cnt0 + s_c1[jt];
    const int gap  = MAXNBR - cnt;     // offset for back-segment indices
    const unsigned short* lst = &s_idx[jt * MAXNBR];
    const int c8 = c0 + cg * 8;

    float acc[8] = {};
    int k = 0;
    for (; k + 4 <= cnt; k += 4) {
        int p0 = k + 0; if (p0 >= cnt0) p0 += gap;
        int p1 = k + 1; if (p1 >= cnt0) p1 += gap;
        int p2 = k + 2; if (p2 >= cnt0) p2 += gap;
        int p3 = k + 3; if (p3 >= cnt0) p3 += gap;
        uint4 h0 = *(const uint4*)&g_Sh[(size_t)lst[p0] * NN + c8];
        uint4 h1 = *(const uint4*)&g_Sh[(size_t)lst[p1] * NN + c8];
        uint4 h2 = *(const uint4*)&g_Sh[(size_t)lst[p2] * NN + c8];
        uint4 h3 = *(const uint4*)&g_Sh[(size_t)lst[p3] * NN + c8];
        add8(acc, h0); add8(acc, h1); add8(acc, h2); add8(acc, h3);
    }
    for (; k < cnt; ++k) {
        int p = k; if (p >= cnt0) p += gap;
        uint4 h = *(const uint4*)&g_Sh[(size_t)lst[p] * NN + c8];
        add8(acc, h);
    }

    // numerator (fp16), divide, stage [jt][cl]
    uint4 nh = *(const uint4*)&g_Sh[(size_t)j * NN + c8];
    float num[8];
    {
        float2 p;
        p = __half22float2(*(__half2*)&nh.x); num[0] = p.x; num[1] = p.y;
        p = __half22float2(*(__half2*)&nh.y); num[2] = p.x; num[3] = p.y;
        p = __half22float2(*(__half2*)&nh.z); num[4] = p.x; num[5] = p.y;
        p = __half22float2(*(__half2*)&nh.w); num[6] = p.x; num[7] = p.y;
    }
    float* sp = &stage[jt * 129 + cg * 8];
    #pragma unroll
    for (int q = 0; q < 8; ++q)
        sp[q] = num[q] / acc[q];
    __syncthreads();

    // transposed write: out rows c0+cl (128 rows), 32 contiguous j's each
    #pragma unroll
    for (int w = 0; w < 2; ++w) {
        int e  = tid + w * 512;
        int cl = e >> 3;
        int j4 = (e & 7) * 4;
        float4 v = make_float4(stage[(j4 + 0) * 129 + cl],
                               stage[(j4 + 1) * 129 + cl],
                               stage[(j4 + 2) * 129 + cl],
                               stage[(j4 + 3) * 129 + cl]);
        *(float4*)&out[(size_t)(c0 + cl) * NN + j0 + j4] = v;
    }
}

// ---------------------------------------------------------------------------
extern "C" void kernel_launch(void* const* d_in, const int* in_sizes, int n_in,
                              void* d_out, int out_size) {
    const float* f   = (const float*)d_in[0];   // [128, 4096]
    const float* nbr = (const float*)d_in[1];   // [4096, 4096]
    const float* wq  = (const float*)d_in[2];   // [128]
    const float* wk  = (const float*)d_in[3];   // [128]
    float* out = (float*)d_out;                 // [4096, 4096]

    build_nbr_kernel<<<NN / 4, 256>>>(nbr);
    compute_S_kernel<<<dim3(32, 32), 256>>>(f, wq, wk);
    fused_T_kernel<<<dim3(NN / 128, NN / 32), 512>>>(out);
}

// round 8
// speedup vs baseline: 1.7337x; 1.0493x over previous
#include <cuda_runtime.h>
#include <cuda_fp16.h>

#define NN 4096
#define FD 128
#define MAXNBR 128

// Scratch (device globals; no cudaMalloc allowed). Hot set = 33 MB, L2-resident.
__device__ __half         g_Sh[(size_t)NN * NN];       // 32 MB fp16 S = exp(f^T C f)
__device__ unsigned short g_idx[(size_t)NN * MAXNBR];  // front/back packed lists
__device__ int            g_cnt0[NN];                  // front-segment count
__device__ int            g_cnt1[NN];                  // back-segment count

// fast exp on the FMA pipe (degree-7 poly of 2^g on [-0.5,0.5]); rel err ~1e-8
__device__ __forceinline__ float fexp(float x) {
    float t = x * 1.4426950408889634f;
    int   ni = __float2int_rn(t);
    float g = t - (float)ni;
    float p =           1.5252734e-5f;
    p = fmaf(p, g,      1.5403530e-4f);
    p = fmaf(p, g,      1.3333558e-3f);
    p = fmaf(p, g,      9.6181291e-3f);
    p = fmaf(p, g,      5.5504109e-2f);
    p = fmaf(p, g,      2.4022651e-1f);
    p = fmaf(p, g,      6.9314718e-1f);
    p = fmaf(p, g,      1.0f);
    return p * __int_as_float((ni + 127) << 23);
}

__device__ __forceinline__ unsigned tf32_rna(float x) {
    unsigned r;
    asm("cvt.rna.tf32.f32 %0, %1;" : "=r"(r) : "f"(x));
    return r;
}

__device__ __forceinline__ void mma_16n8k8(float d[4], const unsigned a[4],
                                           const unsigned b[2]) {
    asm volatile(
        "mma.sync.aligned.m16n8k8.row.col.f32.tf32.tf32.f32 "
        "{%0,%1,%2,%3}, {%4,%5,%6,%7}, {%8,%9}, {%0,%1,%2,%3};"
        : "+f"(d[0]), "+f"(d[1]), "+f"(d[2]), "+f"(d[3])
        : "r"(a[0]), "r"(a[1]), "r"(a[2]), "r"(a[3]), "r"(b[0]), "r"(b[1]));
}

// ---------------------------------------------------------------------------
// Kernel 0: neighbor-list build, sparsity fast-path.
// 2 warps per row (front/back 2048-col halves). One ballot on any(v4!=0);
// full 4-ballot compaction only when the group has hits (~48% of groups).
// ---------------------------------------------------------------------------
__global__ void build_nbr_kernel(const float* __restrict__ nbr) {
    const int warp = threadIdx.x >> 5;        // 0..7
    const int lane = threadIdx.x & 31;
    const int rloc = warp >> 1;
    const int h    = warp & 1;
    const int j    = blockIdx.x * 4 + rloc;
    const float4* row = (const float4*)(nbr + (size_t)j * NN) + h * 512;
    unsigned short* lst = g_idx + (size_t)j * MAXNBR;
    const unsigned lt = (1u << lane) - 1u;
    const int colbase = h * 2048;

    int base = 0;
    #pragma unroll 1
    for (int step = 0; step < 4; ++step) {
        float4 v[4];
        #pragma unroll
        for (int u = 0; u < 4; ++u)
            v[u] = row[(step * 4 + u) * 32 + lane];      // 4 loads in flight

        #pragma unroll
        for (int u = 0; u < 4; ++u) {
            bool nz = (v[u].x != 0.0f) | (v[u].y != 0.0f) |
                      (v[u].z != 0.0f) | (v[u].w != 0.0f);
            unsigned any = __ballot_sync(0xFFFFFFFFu, nz);
            if (any == 0u) continue;                     // warp-uniform skip

            int col = colbase + ((step * 4 + u) * 32 + lane) * 4;
            unsigned m0 = __ballot_sync(0xFFFFFFFFu, v[u].x != 0.0f);
            unsigned m1 = __ballot_sync(0xFFFFFFFFu, v[u].y != 0.0f);
            unsigned m2 = __ballot_sync(0xFFFFFFFFu, v[u].z != 0.0f);
            unsigned m3 = __ballot_sync(0xFFFFFFFFu, v[u].w != 0.0f);
            int t0 = __popc(m0), t1 = __popc(m1), t2 = __popc(m2), t3 = __popc(m3);
            int p0 = base + __popc(m0 & lt);
            int p1 = base + t0 + __popc(m1 & lt);
            int p2 = base + t0 + t1 + __popc(m2 & lt);
            int p3 = base + t0 + t1 + t2 + __popc(m3 & lt);
            if (h == 0) {
                if ((m0 >> lane) & 1 && p0 < MAXNBR) lst[p0] = (unsigned short)(col + 0);
                if ((m1 >> lane) & 1 && p1 < MAXNBR) lst[p1] = (unsigned short)(col + 1);
                if ((m2 >> lane) & 1 && p2 < MAXNBR) lst[p2] = (unsigned short)(col + 2);
                if ((m3 >> lane) & 1 && p3 < MAXNBR) lst[p3] = (unsigned short)(col + 3);
            } else {
                if ((m0 >> lane) & 1 && p0 < MAXNBR) lst[MAXNBR - 1 - p0] = (unsigned short)(col + 0);
                if ((m1 >> lane) & 1 && p1 < MAXNBR) lst[MAXNBR - 1 - p1] = (unsigned short)(col + 1);
                if ((m2 >> lane) & 1 && p2 < MAXNBR) lst[MAXNBR - 1 - p2] = (unsigned short)(col + 2);
                if ((m3 >> lane) & 1 && p3 < MAXNBR) lst[MAXNBR - 1 - p3] = (unsigned short)(col + 3);
            }
            base += t0 + t1 + t2 + t3;
        }
    }
    if (lane == 0) {
        int c = min(base, MAXNBR);
        if (h == 0) g_cnt0[j] = c; else g_cnt1[j] = c;
    }
}

// ---------------------------------------------------------------------------
// Kernel 1: S = exp(f^T diag(wq*wk) f), symmetric — tf32 tensor-core GEMM.
// 128x128 tile per CTA, 8 warps (2x4), m16n8k8, K-chunk 32 (4 mainloop iters),
// poly exp, fp16-only store (primary + smem-staged mirror).
// ---------------------------------------------------------------------------
__global__ void __launch_bounds__(256, 2)
compute_S_kernel(const float* __restrict__ f,
                 const float* __restrict__ wq,
                 const float* __restrict__ wk) {
    const int ti = blockIdx.y;
    const int tj = blockIdx.x;
    if (tj < ti) return;   // upper triangle (mirror written below)

    __shared__ float s_raw[2 * 32 * 132];   // As[32][132] | Bs[32][132] (33.8 KB)
    __shared__ float cs[FD];
    float* As = s_raw;
    float* Bs = s_raw + 32 * 132;

    const int tid  = threadIdx.x;
    const int warp = tid >> 5;
    const int lane = tid & 31;
    const int gID  = lane >> 2;
    const int tig  = lane & 3;
    const int wr   = warp >> 2;
    const int wc   = warp & 3;
    const int iw   = wr * 64;
    const int jw   = wc * 32;
    const int i0   = ti * 128;
    const int j0   = tj * 128;

    if (tid < FD) cs[tid] = wq[tid] * wk[tid];
    __syncthreads();

    float acc[4][4][4] = {};

    #pragma unroll 1
    for (int kb = 0; kb < 4; ++kb) {          // 4 chunks of 32 k-slices
        #pragma unroll
        for (int r = 0; r < 4; ++r) {
            int e  = tid + r * 256;            // 0..1023 f4 slots
            int d2 = e >> 5;                   // 0..31
            int c4 = (e & 31) * 4;
            int d  = kb * 32 + d2;
            float cc = cs[d];
            float4 va = *(const float4*)&f[(size_t)d * NN + i0 + c4];
            unsigned* ap = (unsigned*)&As[d2 * 132 + c4];
            ap[0] = tf32_rna(va.x * cc); ap[1] = tf32_rna(va.y * cc);
            ap[2] = tf32_rna(va.z * cc); ap[3] = tf32_rna(va.w * cc);
            float4 vb = *(const float4*)&f[(size_t)d * NN + j0 + c4];
            unsigned* bp = (unsigned*)&Bs[d2 * 132 + c4];
            bp[0] = tf32_rna(vb.x); bp[1] = tf32_rna(vb.y);
            bp[2] = tf32_rna(vb.z); bp[3] = tf32_rna(vb.w);
        }
        __syncthreads();

        #pragma unroll
        for (int k8 = 0; k8 < 4; ++k8) {
            const int kr0 = k8 * 8 + tig;
            unsigned a[4][4];
            #pragma unroll
            for (int mi = 0; mi < 4; ++mi) {
                int ib = iw + mi * 16 + gID;
                a[mi][0] = ((unsigned*)As)[(kr0    ) * 132 + ib];
                a[mi][1] = ((unsigned*)As)[(kr0    ) * 132 + ib + 8];
                a[mi][2] = ((unsigned*)As)[(kr0 + 4) * 132 + ib];
                a[mi][3] = ((unsigned*)As)[(kr0 + 4) * 132 + ib + 8];
            }
            unsigned b[4][2];
            #pragma unroll
            for (int ni = 0; ni < 4; ++ni) {
                int jb = jw + ni * 8 + gID;
                b[ni][0] = ((unsigned*)Bs)[(kr0    ) * 132 + jb];
                b[ni][1] = ((unsigned*)Bs)[(kr0 + 4) * 132 + jb];
            }
            #pragma unroll
            for (int mi = 0; mi < 4; ++mi)
                #pragma unroll
                for (int ni = 0; ni < 4; ++ni)
                    mma_16n8k8(acc[mi][ni], a[mi], b[ni]);
        }
        __syncthreads();
    }

    #pragma unroll
    for (int mi = 0; mi < 4; ++mi)
        #pragma unroll
        for (int ni = 0; ni < 4; ++ni)
            #pragma unroll
            for (int r = 0; r < 4; ++r)
                acc[mi][ni][r] = fexp(acc[mi][ni][r]);

    // primary tile store: fp16 half2 per fragment pair
    #pragma unroll
    for (int mi = 0; mi < 4; ++mi) {
        #pragma unroll
        for (int h = 0; h < 2; ++h) {
            int row = i0 + iw + mi * 16 + gID + h * 8;
            size_t rbase = (size_t)row * NN + j0;
            #pragma unroll
            for (int ni = 0; ni < 4; ++ni) {
                int col = jw + ni * 8 + 2 * tig;
                __half2 hh = __floats2half2_rn(acc[mi][ni][h * 2 + 0],
                                               acc[mi][ni][h * 2 + 1]);
                *(unsigned*)&g_Sh[rbase + col] = *(unsigned*)&hh;
            }
        }
    }

    // mirror tile (ti != tj): stage 32 tile-cols at a time
    if (ti != tj) {
        float* st = s_raw;   // st[c_local 0..31][row 0..127], stride 132
        #pragma unroll 1
        for (int q = 0; q < 4; ++q) {
            __syncthreads();
            if (wc == q) {
                #pragma unroll
                for (int mi = 0; mi < 4; ++mi)
                    #pragma unroll
                    for (int h = 0; h < 2; ++h) {
                        int rt = iw + mi * 16 + gID + h * 8;
                        #pragma unroll
                        for (int ni = 0; ni < 4; ++ni) {
                            int cl = ni * 8 + 2 * tig;
                            st[(cl + 0) * 132 + rt] = acc[mi][ni][h * 2 + 0];
                            st[(cl + 1) * 132 + rt] = acc[mi][ni][h * 2 + 1];
                        }
                    }
            }
            __syncthreads();
            #pragma unroll
            for (int w = 0; w < 4; ++w) {
                int e4 = tid + w * 256;
                int jl = e4 >> 5;
                int i4 = (e4 & 31) * 4;
                float4 v = *(float4*)&st[jl * 132 + i4];
                size_t rbase = (size_t)(j0 + q * 32 + jl) * NN + i0;
                __half2 h0 = __floats2half2_rn(v.x, v.y);
                __half2 h1 = __floats2half2_rn(v.z, v.w);
                uint2 u = make_uint2(*(unsigned*)&h0, *(unsigned*)&h1);
                *(uint2*)&g_Sh[rbase + i4] = u;
            }
        }
    }
}

// ---------------------------------------------------------------------------
// Kernel 2 (FUSED gather + divide + transposed write), all-fp16 source:
// CTA = 32 j's x 128 cols, 512 threads; thread = (1 j, 8 cols), MLP 8.
// ---------------------------------------------------------------------------
__device__ __forceinline__ void add8(float* acc, uint4 h) {
    float2 p;
    p = __half22float2(*(__half2*)&h.x); acc[0] += p.x; acc[1] += p.y;
    p = __half22float2(*(__half2*)&h.y); acc[2] += p.x; acc[3] += p.y;
    p = __half22float2(*(__half2*)&h.z); acc[4] += p.x; acc[5] += p.y;
    p = __half22float2(*(__half2*)&h.w); acc[6] += p.x; acc[7] += p.y;
}

__global__ void __launch_bounds__(512)
fused_T_kernel(float* __restrict__ out) {
    __shared__ unsigned short s_idx[32 * MAXNBR];   // 8 KB
    __shared__ int            s_c0[32];
    __shared__ int            s_c1[32];
    __shared__ float          stage[32 * 129];      // 16.5 KB  [jt][cl]

    const int tid = threadIdx.x;
    const int cg  = tid & 15;
    const int jt  = tid >> 4;
    const int c0  = blockIdx.x * 128;
    const int j0  = blockIdx.y * 32;

    {
        const uint4* src = (const uint4*)(g_idx + (size_t)j0 * MAXNBR);
        ((uint4*)s_idx)[tid] = src[tid];
        if (tid < 32) { s_c0[tid] = g_cnt0[j0 + tid]; s_c1[tid] = g_cnt1[j0 + tid]; }
    }
    __syncthreads();

    const int j    = j0 + jt;
    const int cnt0 = s_c0[jt];
    const int cnt  = cnt0 + s_c1[jt];
    const int gap  = MAXNBR - cnt;
    const unsigned short* lst = &s_idx[jt * MAXNBR];
    const int c8 = c0 + cg * 8;

    float acc[8] = {};
    int k = 0;
    for (; k + 8 <= cnt; k += 8) {
        uint4 hv[8];
        #pragma unroll
        for (int u = 0; u < 8; ++u) {
            int p = k + u; if (p >= cnt0) p += gap;
            hv[u] = *(const uint4*)&g_Sh[(size_t)lst[p] * NN + c8];
        }
        #pragma unroll
        for (int u = 0; u < 8; ++u) add8(acc, hv[u]);
    }
    for (; k + 4 <= cnt; k += 4) {
        uint4 hv[4];
        #pragma unroll
        for (int u = 0; u < 4; ++u) {
            int p = k + u; if (p >= cnt0) p += gap;
            hv[u] = *(const uint4*)&g_Sh[(size_t)lst[p] * NN + c8];
        }
        #pragma unroll
        for (int u = 0; u < 4; ++u) add8(acc, hv[u]);
    }
    for (; k < cnt; ++k) {
        int p = k; if (p >= cnt0) p += gap;
        uint4 h = *(const uint4*)&g_Sh[(size_t)lst[p] * NN + c8];
        add8(acc, h);
    }

    // numerator (fp16), divide, stage [jt][cl]
    uint4 nh = *(const uint4*)&g_Sh[(size_t)j * NN + c8];
    float num[8];
    {
        float2 p;
        p = __half22float2(*(__half2*)&nh.x); num[0] = p.x; num[1] = p.y;
        p = __half22float2(*(__half2*)&nh.y); num[2] = p.x; num[3] = p.y;
        p = __half22float2(*(__half2*)&nh.z); num[4] = p.x; num[5] = p.y;
        p = __half22float2(*(__half2*)&nh.w); num[6] = p.x; num[7] = p.y;
    }
    float* sp = &stage[jt * 129 + cg * 8];
    #pragma unroll
    for (int q = 0; q < 8; ++q)
        sp[q] = num[q] / acc[q];
    __syncthreads();

    // transposed write: out rows c0+cl (128 rows), 32 contiguous j's each
    #pragma unroll
    for (int w = 0; w < 2; ++w) {
        int e  = tid + w * 512;
        int cl = e >> 3;
        int j4 = (e & 7) * 4;
        float4 v = make_float4(stage[(j4 + 0) * 129 + cl],
                               stage[(j4 + 1) * 129 + cl],
                               stage[(j4 + 2) * 129 + cl],
                               stage[(j4 + 3) * 129 + cl]);
        *(float4*)&out[(size_t)(c0 + cl) * NN + j0 + j4] = v;
    }
}

// ---------------------------------------------------------------------------
extern "C" void kernel_launch(void* const* d_in, const int* in_sizes, int n_in,
                              void* d_out, int out_size) {
    const float* f   = (const float*)d_in[0];   // [128, 4096]
    const float* nbr = (const float*)d_in[1];   // [4096, 4096]
    const float* wq  = (const float*)d_in[2];   // [128]
    const float* wk  = (const float*)d_in[3];   // [128]
    float* out = (float*)d_out;                 // [4096, 4096]

    build_nbr_kernel<<<NN / 4, 256>>>(nbr);
    compute_S_kernel<<<dim3(32, 32), 256>>>(f, wq, wk);
    fused_T_kernel<<<dim3(NN / 128, NN / 32), 512>>>(out);
}

// round 9
// speedup vs baseline: 1.8305x; 1.0559x over previous
#include <cuda_runtime.h>
#include <cuda_fp16.h>

#define NN 4096
#define FD 128
#define MAXNBR 128
#define NTILE 32                 // 4096/128 S-tiles per dim
#define NTRI  528                // NTILE*(NTILE+1)/2 upper-tri tiles
#define NBLD  1024               // build blocks (4 rows each)

// Scratch (device globals; no cudaMalloc allowed). Hot set = 33 MB, L2-resident.
__device__ __half         g_Sh[(size_t)NN * NN];       // 32 MB fp16 S = exp(f^T C f)
__device__ unsigned short g_idx[(size_t)NN * MAXNBR];  // front/back packed lists
__device__ int            g_cnt0[NN];                  // front-segment count
__device__ int            g_cnt1[NN];                  // back-segment count

// fast exp on the FMA pipe (degree-7 poly of 2^g on [-0.5,0.5]); rel err ~1e-8
__device__ __forceinline__ float fexp(float x) {
    float t = x * 1.4426950408889634f;
    int   ni = __float2int_rn(t);
    float g = t - (float)ni;
    float p =           1.5252734e-5f;
    p = fmaf(p, g,      1.5403530e-4f);
    p = fmaf(p, g,      1.3333558e-3f);
    p = fmaf(p, g,      9.6181291e-3f);
    p = fmaf(p, g,      5.5504109e-2f);
    p = fmaf(p, g,      2.4022651e-1f);
    p = fmaf(p, g,      6.9314718e-1f);
    p = fmaf(p, g,      1.0f);
    return p * __int_as_float((ni + 127) << 23);
}

__device__ __forceinline__ unsigned tf32_rna(float x) {
    unsigned r;
    asm("cvt.rna.tf32.f32 %0, %1;" : "=r"(r) : "f"(x));
    return r;
}

__device__ __forceinline__ void mma_16n8k8(float d[4], const unsigned a[4],
                                           const unsigned b[2]) {
    asm volatile(
        "mma.sync.aligned.m16n8k8.row.col.f32.tf32.tf32.f32 "
        "{%0,%1,%2,%3}, {%4,%5,%6,%7}, {%8,%9}, {%0,%1,%2,%3};"
        : "+f"(d[0]), "+f"(d[1]), "+f"(d[2]), "+f"(d[3])
        : "r"(a[0]), "r"(a[1]), "r"(a[2]), "r"(a[3]), "r"(b[0]), "r"(b[1]));
}

// ---------------------------------------------------------------------------
// build part: neighbor-list scan for 4 rows (2 warps/row, front/back halves),
// ballot fast-path on all-zero float4 groups, MLP 8.
// ---------------------------------------------------------------------------
__device__ void build_rows(const float* __restrict__ nbr, int blk) {
    const int warp = threadIdx.x >> 5;        // 0..7
    const int lane = threadIdx.x & 31;
    const int rloc = warp >> 1;
    const int h    = warp & 1;
    const int j    = blk * 4 + rloc;
    const float4* row = (const float4*)(nbr + (size_t)j * NN) + h * 512;
    unsigned short* lst = g_idx + (size_t)j * MAXNBR;
    const unsigned lt = (1u << lane) - 1u;
    const int colbase = h * 2048;

    int base = 0;
    #pragma unroll 1
    for (int step = 0; step < 2; ++step) {
        float4 v[8];
        #pragma unroll
        for (int u = 0; u < 8; ++u)
            v[u] = row[(step * 8 + u) * 32 + lane];      // 8 loads in flight

        #pragma unroll
        for (int u = 0; u < 8; ++u) {
            bool nz = (v[u].x != 0.0f) | (v[u].y != 0.0f) |
                      (v[u].z != 0.0f) | (v[u].w != 0.0f);
            unsigned any = __ballot_sync(0xFFFFFFFFu, nz);
            if (any == 0u) continue;                     // warp-uniform skip

            int col = colbase + ((step * 8 + u) * 32 + lane) * 4;
            unsigned m0 = __ballot_sync(0xFFFFFFFFu, v[u].x != 0.0f);
            unsigned m1 = __ballot_sync(0xFFFFFFFFu, v[u].y != 0.0f);
            unsigned m2 = __ballot_sync(0xFFFFFFFFu, v[u].z != 0.0f);
            unsigned m3 = __ballot_sync(0xFFFFFFFFu, v[u].w != 0.0f);
            int t0 = __popc(m0), t1 = __popc(m1), t2 = __popc(m2), t3 = __popc(m3);
            int p0 = base + __popc(m0 & lt);
            int p1 = base + t0 + __popc(m1 & lt);
            int p2 = base + t0 + t1 + __popc(m2 & lt);
            int p3 = base + t0 + t1 + t2 + __popc(m3 & lt);
            if (h == 0) {
                if ((m0 >> lane) & 1 && p0 < MAXNBR) lst[p0] = (unsigned short)(col + 0);
                if ((m1 >> lane) & 1 && p1 < MAXNBR) lst[p1] = (unsigned short)(col + 1);
                if ((m2 >> lane) & 1 && p2 < MAXNBR) lst[p2] = (unsigned short)(col + 2);
                if ((m3 >> lane) & 1 && p3 < MAXNBR) lst[p3] = (unsigned short)(col + 3);
            } else {
                if ((m0 >> lane) & 1 && p0 < MAXNBR) lst[MAXNBR - 1 - p0] = (unsigned short)(col + 0);
                if ((m1 >> lane) & 1 && p1 < MAXNBR) lst[MAXNBR - 1 - p1] = (unsigned short)(col + 1);
                if ((m2 >> lane) & 1 && p2 < MAXNBR) lst[MAXNBR - 1 - p2] = (unsigned short)(col + 2);
                if ((m3 >> lane) & 1 && p3 < MAXNBR) lst[MAXNBR - 1 - p3] = (unsigned short)(col + 3);
            }
            base += t0 + t1 + t2 + t3;
        }
    }
    if (lane == 0) {
        int c = min(base, MAXNBR);
        if (h == 0) g_cnt0[j] = c; else g_cnt1[j] = c;
    }
}

// ---------------------------------------------------------------------------
// Kernel A (FUSED build + S): blocks [0, NTRI) compute S-tiles (tensor-bound),
// blocks [NTRI, NTRI+NBLD) scan the adjacency (DRAM-bound). The two workloads
// overlap on-chip instead of running serially.
// ---------------------------------------------------------------------------
__global__ void __launch_bounds__(256, 2)
build_and_S_kernel(const float* __restrict__ f,
                   const float* __restrict__ nbr,
                   const float* __restrict__ wq,
                   const float* __restrict__ wk) {
    if (blockIdx.x >= NTRI) {           // ---- build partition ----
        build_rows(nbr, blockIdx.x - NTRI);
        return;
    }

    // ---- S partition: map linear triangular index -> (ti, tj), tj >= ti ----
    const int t = blockIdx.x;
    int ti = (int)((65.0f - sqrtf(4225.0f - 8.0f * (float)t)) * 0.5f);
    while (ti * (65 - ti) / 2 > t) --ti;
    while ((ti + 1) * (64 - ti) / 2 <= t) ++ti;
    const int tj = ti + (t - ti * (65 - ti) / 2);

    __shared__ float s_raw[2 * 32 * 132];   // As[32][132] | Bs[32][132] (33.8 KB)
    __shared__ float cs[FD];
    float* As = s_raw;
    float* Bs = s_raw + 32 * 132;

    const int tid  = threadIdx.x;
    const int warp = tid >> 5;
    const int lane = tid & 31;
    const int gID  = lane >> 2;
    const int tig  = lane & 3;
    const int wr   = warp >> 2;
    const int wc   = warp & 3;
    const int iw   = wr * 64;
    const int jw   = wc * 32;
    const int i0   = ti * 128;
    const int j0   = tj * 128;

    if (tid < FD) cs[tid] = wq[tid] * wk[tid];
    __syncthreads();

    float acc[4][4][4] = {};

    #pragma unroll 1
    for (int kb = 0; kb < 4; ++kb) {          // 4 chunks of 32 k-slices
        #pragma unroll
        for (int r = 0; r < 4; ++r) {
            int e  = tid + r * 256;
            int d2 = e >> 5;
            int c4 = (e & 31) * 4;
            int d  = kb * 32 + d2;
            float cc = cs[d];
            float4 va = *(const float4*)&f[(size_t)d * NN + i0 + c4];
            unsigned* ap = (unsigned*)&As[d2 * 132 + c4];
            ap[0] = tf32_rna(va.x * cc); ap[1] = tf32_rna(va.y * cc);
            ap[2] = tf32_rna(va.z * cc); ap[3] = tf32_rna(va.w * cc);
            float4 vb = *(const float4*)&f[(size_t)d * NN + j0 + c4];
            unsigned* bp = (unsigned*)&Bs[d2 * 132 + c4];
            bp[0] = tf32_rna(vb.x); bp[1] = tf32_rna(vb.y);
            bp[2] = tf32_rna(vb.z); bp[3] = tf32_rna(vb.w);
        }
        __syncthreads();

        #pragma unroll
        for (int k8 = 0; k8 < 4; ++k8) {
            const int kr0 = k8 * 8 + tig;
            unsigned a[4][4];
            #pragma unroll
            for (int mi = 0; mi < 4; ++mi) {
                int ib = iw + mi * 16 + gID;
                a[mi][0] = ((unsigned*)As)[(kr0    ) * 132 + ib];
                a[mi][1] = ((unsigned*)As)[(kr0    ) * 132 + ib + 8];
                a[mi][2] = ((unsigned*)As)[(kr0 + 4) * 132 + ib];
                a[mi][3] = ((unsigned*)As)[(kr0 + 4) * 132 + ib + 8];
            }
            unsigned b[4][2];
            #pragma unroll
            for (int ni = 0; ni < 4; ++ni) {
                int jb = jw + ni * 8 + gID;
                b[ni][0] = ((unsigned*)Bs)[(kr0    ) * 132 + jb];
                b[ni][1] = ((unsigned*)Bs)[(kr0 + 4) * 132 + jb];
            }
            #pragma unroll
            for (int mi = 0; mi < 4; ++mi)
                #pragma unroll
                for (int ni = 0; ni < 4; ++ni)
                    mma_16n8k8(acc[mi][ni], a[mi], b[ni]);
        }
        __syncthreads();
    }

    #pragma unroll
    for (int mi = 0; mi < 4; ++mi)
        #pragma unroll
        for (int ni = 0; ni < 4; ++ni)
            #pragma unroll
            for (int r = 0; r < 4; ++r)
                acc[mi][ni][r] = fexp(acc[mi][ni][r]);

    // primary tile store: fp16 half2 per fragment pair
    #pragma unroll
    for (int mi = 0; mi < 4; ++mi) {
        #pragma unroll
        for (int h = 0; h < 2; ++h) {
            int row = i0 + iw + mi * 16 + gID + h * 8;
            size_t rbase = (size_t)row * NN + j0;
            #pragma unroll
            for (int ni = 0; ni < 4; ++ni) {
                int col = jw + ni * 8 + 2 * tig;
                __half2 hh = __floats2half2_rn(acc[mi][ni][h * 2 + 0],
                                               acc[mi][ni][h * 2 + 1]);
                *(unsigned*)&g_Sh[rbase + col] = *(unsigned*)&hh;
            }
        }
    }

    // mirror tile (ti != tj): stage 32 tile-cols at a time
    if (ti != tj) {
        float* st = s_raw;   // st[c_local 0..31][row 0..127], stride 132
        #pragma unroll 1
        for (int q = 0; q < 4; ++q) {
            __syncthreads();
            if (wc == q) {
                #pragma unroll
                for (int mi = 0; mi < 4; ++mi)
                    #pragma unroll
                    for (int h = 0; h < 2; ++h) {
                        int rt = iw + mi * 16 + gID + h * 8;
                        #pragma unroll
                        for (int ni = 0; ni < 4; ++ni) {
                            int cl = ni * 8 + 2 * tig;
                            st[(cl + 0) * 132 + rt] = acc[mi][ni][h * 2 + 0];
                            st[(cl + 1) * 132 + rt] = acc[mi][ni][h * 2 + 1];
                        }
                    }
            }
            __syncthreads();
            #pragma unroll
            for (int w = 0; w < 4; ++w) {
                int e4 = tid + w * 256;
                int jl = e4 >> 5;
                int i4 = (e4 & 31) * 4;
                float4 v = *(float4*)&st[jl * 132 + i4];
                size_t rbase = (size_t)(j0 + q * 32 + jl) * NN + i0;
                __half2 h0 = __floats2half2_rn(v.x, v.y);
                __half2 h1 = __floats2half2_rn(v.z, v.w);
                uint2 u = make_uint2(*(unsigned*)&h0, *(unsigned*)&h1);
                *(uint2*)&g_Sh[rbase + i4] = u;
            }
        }
    }
}

// ---------------------------------------------------------------------------
// Kernel B (FUSED gather + divide + transposed write), all-fp16 source:
// CTA = 32 j's x 128 cols, 512 threads; thread = (1 j, 8 cols), MLP 8.
// ---------------------------------------------------------------------------
__device__ __forceinline__ void add8(float* acc, uint4 h) {
    float2 p;
    p = __half22float2(*(__half2*)&h.x); acc[0] += p.x; acc[1] += p.y;
    p = __half22float2(*(__half2*)&h.y); acc[2] += p.x; acc[3] += p.y;
    p = __half22float2(*(__half2*)&h.z); acc[4] += p.x; acc[5] += p.y;
    p = __half22float2(*(__half2*)&h.w); acc[6] += p.x; acc[7] += p.y;
}

__global__ void __launch_bounds__(512)
fused_T_kernel(float* __restrict__ out) {
    __shared__ unsigned short s_idx[32 * MAXNBR];   // 8 KB
    __shared__ int            s_c0[32];
    __shared__ int            s_c1[32];
    __shared__ float          stage[32 * 129];      // 16.5 KB  [jt][cl]

    const int tid = threadIdx.x;
    const int cg  = tid & 15;
    const int jt  = tid >> 4;
    const int c0  = blockIdx.x * 128;
    const int j0  = blockIdx.y * 32;

    {
        const uint4* src = (const uint4*)(g_idx + (size_t)j0 * MAXNBR);
        ((uint4*)s_idx)[tid] = src[tid];
        if (tid < 32) { s_c0[tid] = g_cnt0[j0 + tid]; s_c1[tid] = g_cnt1[j0 + tid]; }
    }
    __syncthreads();

    const int j    = j0 + jt;
    const int cnt0 = s_c0[jt];
    const int cnt  = cnt0 + s_c1[jt];
    const int gap  = MAXNBR - cnt;
    const unsigned short* lst = &s_idx[jt * MAXNBR];
    const int c8 = c0 + cg * 8;

    float acc[8] = {};
    int k = 0;
    for (; k + 8 <= cnt; k += 8) {
        uint4 hv[8];
        #pragma unroll
        for (int u = 0; u < 8; ++u) {
            int p = k + u; if (p >= cnt0) p += gap;
            hv[u] = *(const uint4*)&g_Sh[(size_t)lst[p] * NN + c8];
        }
        #pragma unroll
        for (int u = 0; u < 8; ++u) add8(acc, hv[u]);
    }
    for (; k + 4 <= cnt; k += 4) {
        uint4 hv[4];
        #pragma unroll
        for (int u = 0; u < 4; ++u) {
            int p = k + u; if (p >= cnt0) p += gap;
            hv[u] = *(const uint4*)&g_Sh[(size_t)lst[p] * NN + c8];
        }
        #pragma unroll
        for (int u = 0; u < 4; ++u) add8(acc, hv[u]);
    }
    for (; k < cnt; ++k) {
        int p = k; if (p >= cnt0) p += gap;
        uint4 h = *(const uint4*)&g_Sh[(size_t)lst[p] * NN + c8];
        add8(acc, h);
    }

    // numerator (fp16), divide, stage [jt][cl]
    uint4 nh = *(const uint4*)&g_Sh[(size_t)j * NN + c8];
    float num[8];
    {
        float2 p;
        p = __half22float2(*(__half2*)&nh.x); num[0] = p.x; num[1] = p.y;
        p = __half22float2(*(__half2*)&nh.y); num[2] = p.x; num[3] = p.y;
        p = __half22float2(*(__half2*)&nh.z); num[4] = p.x; num[5] = p.y;
        p = __half22float2(*(__half2*)&nh.w); num[6] = p.x; num[7] = p.y;
    }
    float* sp = &stage[jt * 129 + cg * 8];
    #pragma unroll
    for (int q = 0; q < 8; ++q)
        sp[q] = num[q] / acc[q];
    __syncthreads();

    // transposed write: out rows c0+cl (128 rows), 32 contiguous j's each
    #pragma unroll
    for (int w = 0; w < 2; ++w) {
        int e  = tid + w * 512;
        int cl = e >> 3;
        int j4 = (e & 7) * 4;
        float4 v = make_float4(stage[(j4 + 0) * 129 + cl],
                               stage[(j4 + 1) * 129 + cl],
                               stage[(j4 + 2) * 129 + cl],
                               stage[(j4 + 3) * 129 + cl]);
        *(float4*)&out[(size_t)(c0 + cl) * NN + j0 + j4] = v;
    }
}

// ---------------------------------------------------------------------------
extern "C" void kernel_launch(void* const* d_in, const int* in_sizes, int n_in,
                              void* d_out, int out_size) {
    const float* f   = (const float*)d_in[0];   // [128, 4096]
    const float* nbr = (const float*)d_in[1];   // [4096, 4096]
    const float* wq  = (const float*)d_in[2];   // [128]
    const float* wk  = (const float*)d_in[3];   // [128]
    float* out = (float*)d_out;                 // [4096, 4096]

    build_and_S_kernel<<<NTRI + NBLD, 256>>>(f, nbr, wq, wk);
    fused_T_kernel<<<dim3(NN / 128, NN / 32), 512>>>(out);
}